// round 15
// baseline (speedup 1.0000x reference)
#include <cuda_runtime.h>
#include <cstdint>
#include <math.h>

#define Bdim 64
#define Tdim 512
#define IDIM 512
#define Hdim 512
#define Odim 512

// ---- cluster scan config (4-CTA clusters, R13 settings) ----
#define CSZ 4               // CTAs per cluster
#define NCL 32              // clusters (2 batches each)
#define ROWS_C 128          // rows of M per CTA
#define BPCL 2              // batches per cluster
#define KHALF 256           // K elements kept in SMEM (rest in registers)

// ---- fallback (grid-barrier) config ----
#define NBLK 128
#define RPB  16
#define BPB  16

// padded k4-major fragment width (bank-conflict-free for stride-2 k4 writes)
#define FW 130

typedef unsigned long long u64t;

// Device scratch (no allocations allowed)
__device__ float g_xin[(size_t)Bdim * Tdim * Hdim];  // 64 MB
__device__ float g_M[512 * 512];                     // W_y @ W_out
__device__ float g_r0[Bdim * 512];                   // last_logits @ W_y^T + b_y
__device__ float g_c[512];                           // W_y b_out + b_y

// Grid barrier state (fallback path)
__device__ unsigned g_count = 0;
__device__ unsigned g_gen = 0;

__device__ __forceinline__ void gridbar() {
    __syncthreads();
    if (threadIdx.x == 0) {
        unsigned gen = *(volatile unsigned*)&g_gen;
        __threadfence();
        unsigned arr = atomicAdd(&g_count, 1u);
        if (arr == NBLK - 1) {
            *(volatile unsigned*)&g_count = 0u;
            __threadfence();
            atomicAdd(&g_gen, 1u);
        } else {
            while (*(volatile unsigned*)&g_gen == gen) { __nanosleep(64); }
        }
        __threadfence();
    }
    __syncthreads();
}

__device__ __forceinline__ uint32_t smem_u32(const void* p) {
    uint32_t a;
    asm("{ .reg .u64 t; cvta.to.shared.u64 t, %1; cvt.u32.u64 %0, t; }"
        : "=r"(a) : "l"(p));
    return a;
}

__device__ __forceinline__ void cluster_arrive() {
    asm volatile("barrier.cluster.arrive.aligned;" ::: "memory");
}
__device__ __forceinline__ void cluster_wait() {
    asm volatile("barrier.cluster.wait.aligned;" ::: "memory");
}

__device__ __forceinline__ void push_all4(uint32_t laddr, float v) {
#pragma unroll
    for (int pr = 0; pr < CSZ; pr++) {
        uint32_t raddr;
        asm volatile("mapa.shared::cluster.u32 %0, %1, %2;"
                     : "=r"(raddr) : "r"(laddr), "r"(pr));
        asm volatile("st.shared::cluster.f32 [%0], %1;"
                     :: "r"(raddr), "f"(v) : "memory");
    }
}

// ---- packed fp32x2 helpers (Blackwell FFMA2) ----
__device__ __forceinline__ void ffma2(u64t& d, u64t a, u64t b) {
    asm("fma.rn.f32x2 %0, %1, %2, %0;" : "+l"(d) : "l"(a), "l"(b));
}
__device__ __forceinline__ float2 unpk2(u64t v) {
    float2 r;
    asm("mov.b64 {%0, %1}, %2;" : "=f"(r.x), "=f"(r.y) : "l"(v));
    return r;
}

union F4U2 { float4 f; u64t u[2]; };

// ---------------------------------------------------------------------------
// gemm_nt2: C[m,n] = sum_k A[m,k]*W[n,k] + bias[n].  N=K=512; M multiple of 128.
// 128x128 tile, 256 threads, 8x8 microtile, K-pair fma.rn.f32x2.
// Fragments k4-major as float4 (one LDS.128 = two k-pairs), pad FW=130 so
// stride-2 k4 write phases and all read phases are bank-conflict-free.
// 2-stage SMEM ring, ONE __syncthreads per 16-wide K tile.
// ---------------------------------------------------------------------------
__global__ __launch_bounds__(256, 1) void gemm_nt2(const float* __restrict__ A,
                                                   const float* __restrict__ W,
                                                   const float* __restrict__ bias,
                                                   float* __restrict__ C,
                                                   float* __restrict__ ylast) {
    __shared__ float4 As4[2][4][FW];
    __shared__ float4 Bs4[2][4][FW];

    const int tid = threadIdx.x;
    const int bn = blockIdx.x;
    const int bm = blockIdx.y;

    const int lrow = tid >> 1;          // 0..127
    const int lk = (tid & 1) << 3;      // 0 or 8
    const int k4w = (tid & 1) << 1;     // 0 or 2 (k4 index of first write)
    const int tx = tid & 15;
    const int ty = tid >> 4;

    const float* Ag = A + (size_t)(bm * 128 + lrow) * 512 + lk;
    const float* Wg = W + (size_t)(bn * 128 + lrow) * 512 + lk;

    u64t acc2[8][8];
#pragma unroll
    for (int i = 0; i < 8; i++)
#pragma unroll
        for (int j = 0; j < 8; j++) acc2[i][j] = 0ull;

    // Prologue: fill stage 0
    As4[0][k4w + 0][lrow] = *(const float4*)(Ag + 0);
    As4[0][k4w + 1][lrow] = *(const float4*)(Ag + 4);
    Bs4[0][k4w + 0][lrow] = *(const float4*)(Wg + 0);
    Bs4[0][k4w + 1][lrow] = *(const float4*)(Wg + 4);
    __syncthreads();

    for (int it = 0; it < 32; it++) {
        const int st = it & 1;
        const bool more = (it + 1 < 32);
        float4 na0, na1, nw0, nw1;
        if (more) {
            na0 = *(const float4*)(Ag + (it + 1) * 16 + 0);
            na1 = *(const float4*)(Ag + (it + 1) * 16 + 4);
            nw0 = *(const float4*)(Wg + (it + 1) * 16 + 0);
            nw1 = *(const float4*)(Wg + (it + 1) * 16 + 4);
        }

#pragma unroll
        for (int k4 = 0; k4 < 4; k4++) {
            F4U2 a4[8], b4[8];
#pragma unroll
            for (int i = 0; i < 8; i++)
                a4[i].f = As4[st][k4][ty * 8 + i];
#pragma unroll
            for (int j = 0; j < 8; j++)
                b4[j].f = Bs4[st][k4][tx + 16 * j];
#pragma unroll
            for (int i = 0; i < 8; i++)
#pragma unroll
                for (int j = 0; j < 8; j++) {
                    ffma2(acc2[i][j], a4[i].u[0], b4[j].u[0]);
                    ffma2(acc2[i][j], a4[i].u[1], b4[j].u[1]);
                }
        }

        if (more) {
            const int ns = st ^ 1;
            As4[ns][k4w + 0][lrow] = na0;
            As4[ns][k4w + 1][lrow] = na1;
            Bs4[ns][k4w + 0][lrow] = nw0;
            Bs4[ns][k4w + 1][lrow] = nw1;
        }
        __syncthreads();
    }

    float bv[8];
#pragma unroll
    for (int j = 0; j < 8; j++) bv[j] = bias[bn * 128 + tx + 16 * j];

#pragma unroll
    for (int i = 0; i < 8; i++) {
        const int m = bm * 128 + ty * 8 + i;
        const bool last = (ylast != nullptr) && ((m & (Tdim - 1)) == (Tdim - 1));
#pragma unroll
        for (int j = 0; j < 8; j++) {
            const int n = bn * 128 + tx + 16 * j;
            float2 s = unpk2(acc2[i][j]);
            float v = s.x + s.y + bv[j];
            C[(size_t)m * 512 + n] = v;
            if (last) ylast[(size_t)(m >> 9) * 512 + n] = v;
        }
    }
}

// ---------------------------------------------------------------------------
// Old NT SGEMM (kept for the small r0 precompute, M=64).
// ---------------------------------------------------------------------------
#define BM 64
#define BN 64
#define BK 16

__global__ __launch_bounds__(256) void gemm_nt(const float* __restrict__ A,
                                               const float* __restrict__ W,
                                               const float* __restrict__ bias,
                                               float* __restrict__ C) {
    __shared__ float Ast[BK][BM + 4];
    __shared__ float Bst[BK][BN + 4];
    const int bn = blockIdx.x;
    const int bm = blockIdx.y;
    const int tid = threadIdx.x;

    const int lr = tid >> 2;
    const int lc = (tid & 3) << 2;
    const int tx = tid & 15;
    const int ty = tid >> 4;

    float acc[4][4];
#pragma unroll
    for (int i = 0; i < 4; i++)
#pragma unroll
        for (int j = 0; j < 4; j++) acc[i][j] = 0.0f;

    const float* Ab = A + (size_t)(bm * BM) * 512;
    const float* Wb = W + (size_t)(bn * BN) * 512;

    for (int kt = 0; kt < 512; kt += BK) {
        float4 av = *(const float4*)(Ab + (size_t)lr * 512 + kt + lc);
        float4 wv = *(const float4*)(Wb + (size_t)lr * 512 + kt + lc);
        Ast[lc + 0][lr] = av.x; Ast[lc + 1][lr] = av.y;
        Ast[lc + 2][lr] = av.z; Ast[lc + 3][lr] = av.w;
        Bst[lc + 0][lr] = wv.x; Bst[lc + 1][lr] = wv.y;
        Bst[lc + 2][lr] = wv.z; Bst[lc + 3][lr] = wv.w;
        __syncthreads();
#pragma unroll
        for (int kk = 0; kk < BK; kk++) {
            float4 a4 = *(const float4*)&Ast[kk][ty * 4];
            float4 b4 = *(const float4*)&Bst[kk][tx * 4];
#pragma unroll
            for (int i = 0; i < 4; i++) {
                float av_ = (&a4.x)[i];
                acc[i][0] = fmaf(av_, b4.x, acc[i][0]);
                acc[i][1] = fmaf(av_, b4.y, acc[i][1]);
                acc[i][2] = fmaf(av_, b4.z, acc[i][2]);
                acc[i][3] = fmaf(av_, b4.w, acc[i][3]);
            }
        }
        __syncthreads();
    }

    const int n0 = bn * BN + tx * 4;
    float4 bsv = *(const float4*)&bias[n0];
#pragma unroll
    for (int i = 0; i < 4; i++) {
        int m = bm * BM + ty * 4 + i;
        float4 o;
        o.x = acc[i][0] + bsv.x;
        o.y = acc[i][1] + bsv.y;
        o.z = acc[i][2] + bsv.z;
        o.w = acc[i][3] + bsv.w;
        *(float4*)&C[(size_t)m * 512 + n0] = o;
    }
}

// ---------------------------------------------------------------------------
// NN SGEMM for M = W_y @ W_out (512x512x512).
// ---------------------------------------------------------------------------
__global__ __launch_bounds__(256) void gemm_nn_M(const float* __restrict__ A,
                                                 const float* __restrict__ B,
                                                 float* __restrict__ C) {
    __shared__ float Ast[BK][BM + 4];
    __shared__ float Bst[BK][BN + 4];
    const int bn = blockIdx.x;
    const int bm = blockIdx.y;
    const int tid = threadIdx.x;

    const int ar = tid >> 2;
    const int ak = (tid & 3) << 2;
    const int br = tid >> 4;
    const int bc = (tid & 15) << 2;
    const int tx = tid & 15;
    const int ty = tid >> 4;

    float acc[4][4];
#pragma unroll
    for (int i = 0; i < 4; i++)
#pragma unroll
        for (int j = 0; j < 4; j++) acc[i][j] = 0.0f;

    for (int kt = 0; kt < 512; kt += BK) {
        float4 av = *(const float4*)(A + (size_t)(bm * BM + ar) * 512 + kt + ak);
        Ast[ak + 0][ar] = av.x; Ast[ak + 1][ar] = av.y;
        Ast[ak + 2][ar] = av.z; Ast[ak + 3][ar] = av.w;
        float4 bv = *(const float4*)(B + (size_t)(kt + br) * 512 + bn * BN + bc);
        *(float4*)&Bst[br][bc] = bv;
        __syncthreads();
#pragma unroll
        for (int kk = 0; kk < BK; kk++) {
            float4 a4 = *(const float4*)&Ast[kk][ty * 4];
            float4 b4 = *(const float4*)&Bst[kk][tx * 4];
#pragma unroll
            for (int i = 0; i < 4; i++) {
                float av_ = (&a4.x)[i];
                acc[i][0] = fmaf(av_, b4.x, acc[i][0]);
                acc[i][1] = fmaf(av_, b4.y, acc[i][1]);
                acc[i][2] = fmaf(av_, b4.z, acc[i][2]);
                acc[i][3] = fmaf(av_, b4.w, acc[i][3]);
            }
        }
        __syncthreads();
    }

    const int n0 = bn * BN + tx * 4;
#pragma unroll
    for (int i = 0; i < 4; i++) {
        int m = bm * BM + ty * 4 + i;
        float4 o = make_float4(acc[i][0], acc[i][1], acc[i][2], acc[i][3]);
        *(float4*)&C[(size_t)m * 512 + n0] = o;
    }
}

// c[i] = b_y[i] + dot(W_y[i,:], b_out)
__global__ void calc_c_kernel(const float* __restrict__ W_y,
                              const float* __restrict__ b_y,
                              const float* __restrict__ b_out,
                              float* __restrict__ c) {
    int row = blockIdx.x * 8 + (threadIdx.x >> 5);
    int l = threadIdx.x & 31;
    float s = 0.0f;
    for (int j = l; j < 512; j += 32) s += W_y[row * 512 + j] * b_out[j];
#pragma unroll
    for (int off = 16; off; off >>= 1) s += __shfl_xor_sync(0xffffffffu, s, off);
    if (l == 0) c[row] = s + b_y[row];
}

// ---------------------------------------------------------------------------
// Warp matvec tile for the grid-barrier fallback.
// ---------------------------------------------------------------------------
__device__ __forceinline__ float matvec_tile(const float* __restrict__ sW,
                                             const float* __restrict__ sA,
                                             int kc, int bg2, int rg2) {
    const float* wp = sW + (rg2 * 8) * 512 + kc;
    const float* ap = sA + (bg2 * 4) * 512 + kc;
    float acc[32];
#pragma unroll
    for (int a = 0; a < 32; a++) acc[a] = 0.0f;
#pragma unroll
    for (int j = 0; j < 16; j++) {
        const int k = 32 * j;
        float yv[4], wv[8];
#pragma unroll
        for (int i2 = 0; i2 < 4; i2++) yv[i2] = ap[i2 * 512 + k];
#pragma unroll
        for (int p = 0; p < 8; p++) wv[p] = wp[p * 512 + k];
#pragma unroll
        for (int i2 = 0; i2 < 4; i2++)
#pragma unroll
            for (int p = 0; p < 8; p++)
                acc[i2 * 8 + p] = fmaf(yv[i2], wv[p], acc[i2 * 8 + p]);
    }
#pragma unroll
    for (int s = 16; s >= 1; s >>= 1) {
        const bool up = (kc & s);
#pragma unroll
        for (int a = 0; a < s; a++) {
            float send = up ? acc[a] : acc[a + s];
            float recv = __shfl_xor_sync(0xffffffffu, send, s);
            acc[a] = (up ? acc[a + s] : acc[a]) + recv;
        }
    }
    return acc[0];
}

extern __shared__ float smem[];

// ---------------------------------------------------------------------------
// Primary scan (R13 version, measured ~825 us for 512 steps):
// h_t = tanh(xin_t + M h_{t-1} + c), 32 clusters x 4 CTAs, 256 threads.
// K [0,256) weights in row-major SMEM; K [256,512) in registers (k-pairs).
// Split cluster barrier: push -> arrive -> (STG h, prefetch xin) -> wait.
// ---------------------------------------------------------------------------
__global__ __launch_bounds__(256, 1) void jordan_scan_m_cluster4(
    float* __restrict__ out_h) {
    float* sW    = smem;                          // 128 * 256 floats (128 KB)
    float* hbuf0 = smem + ROWS_C * KHALF;         // 2*512
    float* hbuf1 = hbuf0 + BPCL * 512;            // 2*512

    const int tid = threadIdx.x;
    unsigned rank;
    asm("mov.u32 %0, %%cluster_ctarank;" : "=r"(rank));
    const int cid = blockIdx.x / CSZ;
    const int b0 = cid * BPCL;
    const int r0row = (int)rank * ROWS_C;

    const int w = tid >> 5, kc = tid & 31;

    // SMEM weights: K-half [0,256), row-major.
    for (int q = tid; q < ROWS_C * (KHALF / 4); q += 256) {
        int r = q >> 6;
        int k4 = (q & 63) << 2;
        *(float4*)&sW[r * KHALF + k4] =
            *(const float4*)(g_M + (size_t)(r0row + r) * 512 + k4);
    }

    // Register weights: k in [256,512) as packed pairs.
    u64t wreg2[16][4];
#pragma unroll
    for (int r2 = 0; r2 < 16; r2++) {
        const float* mp = g_M + (size_t)(r0row + w * 16 + r2) * 512;
#pragma unroll
        for (int j = 0; j < 4; j++)
            wreg2[r2][j] = *(const u64t*)&mp[KHALF + 2 * kc + 64 * j];
    }

    const int row_l = w * 16 + (kc >> 1);
    const int b_l = kc & 1;
    const int b_idx = b0 + b_l;
    const int r_idx = r0row + row_l;
    const float cv = g_c[r_idx];

    uint32_t laddr[2];
    laddr[0] = smem_u32(&hbuf0[b_l * 512 + r_idx]);
    laddr[1] = smem_u32(&hbuf1[b_l * 512 + r_idx]);

    __syncthreads();
    cluster_arrive();
    cluster_wait();

    // t = 0: h_0 = tanh(xin_0 + r0)
    float xin_cur = g_xin[((size_t)b_idx * Tdim + 0) * Hdim + r_idx];
    {
        float v = tanhf(xin_cur + g_r0[(size_t)b_idx * 512 + r_idx]);
        push_all4(laddr[0], v);
        cluster_arrive();
        out_h[((size_t)b_idx * Tdim + 0) * Hdim + r_idx] = v;
        xin_cur = g_xin[((size_t)b_idx * Tdim + 1) * Hdim + r_idx];
    }

    const float* sWw = sW + (w * 16) * KHALF;

    for (int t = 1; t < Tdim; t++) {
        cluster_wait();   // h_{t-1} visible in hbuf[(t+1)&1]
        const float* hb = ((t & 1) == 1) ? hbuf0 : hbuf1;

        u64t acc2[16][2];
#pragma unroll
        for (int r2 = 0; r2 < 16; r2++) {
            acc2[r2][0] = 0ull;
            acc2[r2][1] = 0ull;
        }

#pragma unroll
        for (int j = 0; j < 4; j++) {
            const int k = 2 * kc + 64 * j;
            const u64t ya = *(const u64t*)&hb[k];
            const u64t yb = *(const u64t*)&hb[512 + k];
#pragma unroll
            for (int r2 = 0; r2 < 16; r2++) {
                const u64t wp = *(const u64t*)&sWw[r2 * KHALF + k];
                ffma2(acc2[r2][0], wp, ya);
                ffma2(acc2[r2][1], wp, yb);
            }
        }
#pragma unroll
        for (int j = 0; j < 4; j++) {
            const int k = KHALF + 2 * kc + 64 * j;
            const u64t ya = *(const u64t*)&hb[k];
            const u64t yb = *(const u64t*)&hb[512 + k];
#pragma unroll
            for (int r2 = 0; r2 < 16; r2++) {
                ffma2(acc2[r2][0], wreg2[r2][j], ya);
                ffma2(acc2[r2][1], wreg2[r2][j], yb);
            }
        }

        float acc_f[32];
#pragma unroll
        for (int r2 = 0; r2 < 16; r2++) {
            float2 s0 = unpk2(acc2[r2][0]);
            float2 s1 = unpk2(acc2[r2][1]);
            acc_f[2 * r2 + 0] = s0.x + s0.y;
            acc_f[2 * r2 + 1] = s1.x + s1.y;
        }

#pragma unroll
        for (int s = 16; s >= 1; s >>= 1) {
            const bool up = (kc & s);
#pragma unroll
            for (int a = 0; a < s; a++) {
                float send = up ? acc_f[a] : acc_f[a + s];
                float recv = __shfl_xor_sync(0xffffffffu, send, s);
                acc_f[a] = (up ? acc_f[a + s] : acc_f[a]) + recv;
            }
        }

        float v = tanhf(acc_f[0] + xin_cur + cv);
        push_all4(laddr[t & 1], v);
        cluster_arrive();
        // Window: off-critical-path work between arrive and next wait.
        out_h[((size_t)b_idx * Tdim + t) * Hdim + r_idx] = v;
        if (t + 1 < Tdim)
            xin_cur = g_xin[((size_t)b_idx * Tdim + (t + 1)) * Hdim + r_idx];
    }
    cluster_wait();   // balance final arrive; keep smem alive for peers
}

// ---------------------------------------------------------------------------
// Fallback scan: grid barrier (128 CTAs), ONE barrier/step.
// ---------------------------------------------------------------------------
__global__ __launch_bounds__(256, 1) void jordan_scan_m(
    float* __restrict__ out_h) {
    float* sM   = smem;
    float* sAct = smem + RPB * 512;

    const int tid = threadIdx.x;
    const int bid = blockIdx.x;
    const int rg = bid & 31;
    const int bg = bid >> 5;
    const int r0 = rg * RPB;
    const int b0 = bg * BPB;

    for (int q = tid; q < RPB * 512 / 4; q += 256)
        ((float4*)sM)[q] = ((const float4*)(g_M + (size_t)r0 * 512))[q];

    const int w = tid >> 5, kc = tid & 31;
    const int bg2 = w >> 1, rg2 = w & 1;
    const int i2 = kc >> 3, p = kc & 7;
    const int b_idx = b0 + bg2 * 4 + i2;
    const int r_idx = r0 + rg2 * 8 + p;
    const float cv = g_c[r_idx];

    const int sb = tid >> 4;
    const int sc = tid & 15;

    __syncthreads();

    {
        float v = tanhf(g_xin[((size_t)b_idx * Tdim + 0) * Hdim + r_idx] +
                        g_r0[(size_t)b_idx * 512 + r_idx]);
        out_h[((size_t)b_idx * Tdim + 0) * Hdim + r_idx] = v;
    }
    __threadfence();
    gridbar();

    for (int t = 1; t < Tdim; t++) {
        {
            const float* src = out_h + ((size_t)(b0 + sb) * Tdim + (t - 1)) * Hdim;
            float4* dst = (float4*)(sAct + sb * 512);
            const float4* s4 = (const float4*)src;
#pragma unroll
            for (int q = 0; q < 8; q++) dst[sc + 16 * q] = s4[sc + 16 * q];
        }
        __syncthreads();

        float v = matvec_tile(sM, sAct, kc, bg2, rg2);
        v = tanhf(v + g_xin[((size_t)b_idx * Tdim + t) * Hdim + r_idx] + cv);
        out_h[((size_t)b_idx * Tdim + t) * Hdim + r_idx] = v;
        __threadfence();
        gridbar();
    }
}

// ---------------------------------------------------------------------------
extern "C" void kernel_launch(void* const* d_in, const int* in_sizes, int n_in,
                              void* d_out, int out_size) {
    const float* emb    = (const float*)d_in[0];
    const float* lastlg = (const float*)d_in[1];
    const float* W_in   = (const float*)d_in[2];
    const float* b_in   = (const float*)d_in[3];
    const float* W_y    = (const float*)d_in[4];
    const float* b_y    = (const float*)d_in[5];
    const float* W_out  = (const float*)d_in[6];
    const float* b_out  = (const float*)d_in[7];

    float* out    = (float*)d_out;
    float* out_h  = out;
    float* out_y  = out + (size_t)Bdim * Tdim * Hdim;
    float* out_yl = out + (size_t)2 * Bdim * Tdim * Hdim;

    float* xin_p; cudaGetSymbolAddress((void**)&xin_p, g_xin);
    float* M_p;   cudaGetSymbolAddress((void**)&M_p, g_M);
    float* r0_p;  cudaGetSymbolAddress((void**)&r0_p, g_r0);
    float* c_p;   cudaGetSymbolAddress((void**)&c_p, g_c);

    // Precomputes
    gemm_nn_M<<<dim3(512 / BN, 512 / BM), 256>>>(W_y, W_out, M_p);
    calc_c_kernel<<<64, 256>>>(W_y, b_y, b_out, c_p);
    gemm_nt<<<dim3(512 / BN, Bdim / BM), 256>>>(lastlg, W_y, b_y, r0_p);

    // Input projection (fast path)
    gemm_nt2<<<dim3(512 / 128, (Bdim * Tdim) / 128), 256>>>(emb, W_in, b_in,
                                                            xin_p, nullptr);

    // ---- scan: try 4-CTA cluster path ----
    const int smem_cluster =
        (ROWS_C * KHALF + 2 * BPCL * 512) * (int)sizeof(float);  // 136 KB
    bool use_cluster =
        (cudaFuncSetAttribute(jordan_scan_m_cluster4,
                              cudaFuncAttributeMaxDynamicSharedMemorySize,
                              smem_cluster) == cudaSuccess);

    cudaLaunchConfig_t cfg = {};
    cfg.gridDim = dim3(CSZ * NCL, 1, 1);
    cfg.blockDim = dim3(256, 1, 1);
    cfg.dynamicSmemBytes = smem_cluster;
    cudaLaunchAttribute attrs[1];
    attrs[0].id = cudaLaunchAttributeClusterDimension;
    attrs[0].val.clusterDim.x = CSZ;
    attrs[0].val.clusterDim.y = 1;
    attrs[0].val.clusterDim.z = 1;
    cfg.attrs = attrs;
    cfg.numAttrs = 1;

    if (use_cluster) {
        int maxClusters = 0;
        cudaError_t st = cudaOccupancyMaxActiveClusters(&maxClusters,
                                                        jordan_scan_m_cluster4,
                                                        &cfg);
        if (st != cudaSuccess || maxClusters < NCL) use_cluster = false;
    }
    (void)cudaGetLastError();

    if (use_cluster) {
        cudaError_t st = cudaLaunchKernelEx(&cfg, jordan_scan_m_cluster4, out_h);
        if (st != cudaSuccess) {
            (void)cudaGetLastError();
            use_cluster = false;
        }
    }
    if (!use_cluster) {
        const int smem_fb = 2 * RPB * 512 * (int)sizeof(float);  // 64 KB
        cudaFuncSetAttribute(jordan_scan_m,
                             cudaFuncAttributeMaxDynamicSharedMemorySize, smem_fb);
        jordan_scan_m<<<NBLK, 256, smem_fb>>>(out_h);
    }

    // Epilogue: y = h @ W_out^T + b_out (+ y_last rows), fast path
    gemm_nt2<<<dim3(512 / 128, (Bdim * Tdim) / 128), 256>>>(out_h, W_out, b_out,
                                                            out_y, out_yl);
}

// round 16
// speedup vs baseline: 1.6108x; 1.6108x over previous
#include <cuda_runtime.h>
#include <cstdint>
#include <math.h>

#define Bdim 64
#define Tdim 512
#define IDIM 512
#define Hdim 512
#define Odim 512

// ---- cluster scan config (4-CTA clusters, R13 settings) ----
#define CSZ 4               // CTAs per cluster
#define NCL 32              // clusters (2 batches each)
#define ROWS_C 128          // rows of M per CTA
#define BPCL 2              // batches per cluster
#define KHALF 256           // K elements kept in SMEM (rest in registers)

// ---- fallback (grid-barrier) config ----
#define NBLK 128
#define RPB  16
#define BPB  16

typedef unsigned long long u64t;

// Device scratch (no allocations allowed)
__device__ float g_xin[(size_t)Bdim * Tdim * Hdim];  // 64 MB
__device__ float g_M[512 * 512];                     // W_y @ W_out
__device__ float g_r0[Bdim * 512];                   // last_logits @ W_y^T + b_y
__device__ float g_c[512];                           // W_y b_out + b_y

// Grid barrier state (fallback path)
__device__ unsigned g_count = 0;
__device__ unsigned g_gen = 0;

__device__ __forceinline__ void gridbar() {
    __syncthreads();
    if (threadIdx.x == 0) {
        unsigned gen = *(volatile unsigned*)&g_gen;
        __threadfence();
        unsigned arr = atomicAdd(&g_count, 1u);
        if (arr == NBLK - 1) {
            *(volatile unsigned*)&g_count = 0u;
            __threadfence();
            atomicAdd(&g_gen, 1u);
        } else {
            while (*(volatile unsigned*)&g_gen == gen) { __nanosleep(64); }
        }
        __threadfence();
    }
    __syncthreads();
}

__device__ __forceinline__ uint32_t smem_u32(const void* p) {
    uint32_t a;
    asm("{ .reg .u64 t; cvta.to.shared.u64 t, %1; cvt.u32.u64 %0, t; }"
        : "=r"(a) : "l"(p));
    return a;
}

__device__ __forceinline__ void cluster_arrive() {
    asm volatile("barrier.cluster.arrive.aligned;" ::: "memory");
}
__device__ __forceinline__ void cluster_wait() {
    asm volatile("barrier.cluster.wait.aligned;" ::: "memory");
}

__device__ __forceinline__ uint32_t mapa_u32(uint32_t laddr, int pr) {
    uint32_t raddr;
    asm volatile("mapa.shared::cluster.u32 %0, %1, %2;"
                 : "=r"(raddr) : "r"(laddr), "r"(pr));
    return raddr;
}

__device__ __forceinline__ void st_cluster_f32(uint32_t raddr, float v) {
    asm volatile("st.shared::cluster.f32 [%0], %1;"
                 :: "r"(raddr), "f"(v) : "memory");
}

// ---- packed fp32x2 helpers (Blackwell FFMA2) ----
__device__ __forceinline__ void ffma2(u64t& d, u64t a, u64t b) {
    asm("fma.rn.f32x2 %0, %1, %2, %0;" : "+l"(d) : "l"(a), "l"(b));
}
__device__ __forceinline__ float2 unpk2(u64t v) {
    float2 r;
    asm("mov.b64 {%0, %1}, %2;" : "=f"(r.x), "=f"(r.y) : "l"(v));
    return r;
}

// ---------------------------------------------------------------------------
// gemm_nt2 (R11 version, measured ~354 us x3): C = A @ W^T + bias.
// 128x128 tile, 256 threads, 8x8 microtile, K-pair fma.rn.f32x2.
// 2-stage SMEM ring, ONE __syncthreads per 16-wide K tile.
// Fragments k2-major as float2 (conflict-free). DO NOT PERTURB (R15 lesson).
// ---------------------------------------------------------------------------
__global__ __launch_bounds__(256, 1) void gemm_nt2(const float* __restrict__ A,
                                                   const float* __restrict__ W,
                                                   const float* __restrict__ bias,
                                                   float* __restrict__ C,
                                                   float* __restrict__ ylast) {
    __shared__ float2 As2[2][8][128];
    __shared__ float2 Bs2[2][8][128];

    const int tid = threadIdx.x;
    const int bn = blockIdx.x;
    const int bm = blockIdx.y;

    const int lrow = tid >> 1;          // 0..127
    const int lk = (tid & 1) << 3;      // 0 or 8
    const int lk2 = (tid & 1) << 2;     // 0 or 4
    const int tx = tid & 15;
    const int ty = tid >> 4;

    const float* Ag = A + (size_t)(bm * 128 + lrow) * 512 + lk;
    const float* Wg = W + (size_t)(bn * 128 + lrow) * 512 + lk;

    u64t acc2[8][8];
#pragma unroll
    for (int i = 0; i < 8; i++)
#pragma unroll
        for (int j = 0; j < 8; j++) acc2[i][j] = 0ull;

    {
        float4 pa0 = *(const float4*)(Ag + 0);
        float4 pa1 = *(const float4*)(Ag + 4);
        float4 pw0 = *(const float4*)(Wg + 0);
        float4 pw1 = *(const float4*)(Wg + 4);
        As2[0][lk2 + 0][lrow] = make_float2(pa0.x, pa0.y);
        As2[0][lk2 + 1][lrow] = make_float2(pa0.z, pa0.w);
        As2[0][lk2 + 2][lrow] = make_float2(pa1.x, pa1.y);
        As2[0][lk2 + 3][lrow] = make_float2(pa1.z, pa1.w);
        Bs2[0][lk2 + 0][lrow] = make_float2(pw0.x, pw0.y);
        Bs2[0][lk2 + 1][lrow] = make_float2(pw0.z, pw0.w);
        Bs2[0][lk2 + 2][lrow] = make_float2(pw1.x, pw1.y);
        Bs2[0][lk2 + 3][lrow] = make_float2(pw1.z, pw1.w);
    }
    __syncthreads();

    for (int it = 0; it < 32; it++) {
        const int st = it & 1;
        const bool more = (it + 1 < 32);
        float4 na0, na1, nw0, nw1;
        if (more) {
            na0 = *(const float4*)(Ag + (it + 1) * 16 + 0);
            na1 = *(const float4*)(Ag + (it + 1) * 16 + 4);
            nw0 = *(const float4*)(Wg + (it + 1) * 16 + 0);
            nw1 = *(const float4*)(Wg + (it + 1) * 16 + 4);
        }

#pragma unroll
        for (int k2 = 0; k2 < 8; k2++) {
            u64t a2[8], b2[8];
#pragma unroll
            for (int i = 0; i < 8; i++)
                a2[i] = *(const u64t*)&As2[st][k2][ty * 8 + i];
#pragma unroll
            for (int j = 0; j < 8; j++)
                b2[j] = *(const u64t*)&Bs2[st][k2][tx + 16 * j];
#pragma unroll
            for (int i = 0; i < 8; i++)
#pragma unroll
                for (int j = 0; j < 8; j++) ffma2(acc2[i][j], a2[i], b2[j]);
        }

        if (more) {
            const int ns = st ^ 1;
            As2[ns][lk2 + 0][lrow] = make_float2(na0.x, na0.y);
            As2[ns][lk2 + 1][lrow] = make_float2(na0.z, na0.w);
            As2[ns][lk2 + 2][lrow] = make_float2(na1.x, na1.y);
            As2[ns][lk2 + 3][lrow] = make_float2(na1.z, na1.w);
            Bs2[ns][lk2 + 0][lrow] = make_float2(nw0.x, nw0.y);
            Bs2[ns][lk2 + 1][lrow] = make_float2(nw0.z, nw0.w);
            Bs2[ns][lk2 + 2][lrow] = make_float2(nw1.x, nw1.y);
            Bs2[ns][lk2 + 3][lrow] = make_float2(nw1.z, nw1.w);
        }
        __syncthreads();
    }

    float bv[8];
#pragma unroll
    for (int j = 0; j < 8; j++) bv[j] = bias[bn * 128 + tx + 16 * j];

#pragma unroll
    for (int i = 0; i < 8; i++) {
        const int m = bm * 128 + ty * 8 + i;
        const bool last = (ylast != nullptr) && ((m & (Tdim - 1)) == (Tdim - 1));
#pragma unroll
        for (int j = 0; j < 8; j++) {
            const int n = bn * 128 + tx + 16 * j;
            float2 s = unpk2(acc2[i][j]);
            float v = s.x + s.y + bv[j];
            C[(size_t)m * 512 + n] = v;
            if (last) ylast[(size_t)(m >> 9) * 512 + n] = v;
        }
    }
}

// ---------------------------------------------------------------------------
// Old NT SGEMM (kept for the small r0 precompute, M=64).
// ---------------------------------------------------------------------------
#define BM 64
#define BN 64
#define BK 16

__global__ __launch_bounds__(256) void gemm_nt(const float* __restrict__ A,
                                               const float* __restrict__ W,
                                               const float* __restrict__ bias,
                                               float* __restrict__ C) {
    __shared__ float Ast[BK][BM + 4];
    __shared__ float Bst[BK][BN + 4];
    const int bn = blockIdx.x;
    const int bm = blockIdx.y;
    const int tid = threadIdx.x;

    const int lr = tid >> 2;
    const int lc = (tid & 3) << 2;
    const int tx = tid & 15;
    const int ty = tid >> 4;

    float acc[4][4];
#pragma unroll
    for (int i = 0; i < 4; i++)
#pragma unroll
        for (int j = 0; j < 4; j++) acc[i][j] = 0.0f;

    const float* Ab = A + (size_t)(bm * BM) * 512;
    const float* Wb = W + (size_t)(bn * BN) * 512;

    for (int kt = 0; kt < 512; kt += BK) {
        float4 av = *(const float4*)(Ab + (size_t)lr * 512 + kt + lc);
        float4 wv = *(const float4*)(Wb + (size_t)lr * 512 + kt + lc);
        Ast[lc + 0][lr] = av.x; Ast[lc + 1][lr] = av.y;
        Ast[lc + 2][lr] = av.z; Ast[lc + 3][lr] = av.w;
        Bst[lc + 0][lr] = wv.x; Bst[lc + 1][lr] = wv.y;
        Bst[lc + 2][lr] = wv.z; Bst[lc + 3][lr] = wv.w;
        __syncthreads();
#pragma unroll
        for (int kk = 0; kk < BK; kk++) {
            float4 a4 = *(const float4*)&Ast[kk][ty * 4];
            float4 b4 = *(const float4*)&Bst[kk][tx * 4];
#pragma unroll
            for (int i = 0; i < 4; i++) {
                float av_ = (&a4.x)[i];
                acc[i][0] = fmaf(av_, b4.x, acc[i][0]);
                acc[i][1] = fmaf(av_, b4.y, acc[i][1]);
                acc[i][2] = fmaf(av_, b4.z, acc[i][2]);
                acc[i][3] = fmaf(av_, b4.w, acc[i][3]);
            }
        }
        __syncthreads();
    }

    const int n0 = bn * BN + tx * 4;
    float4 bsv = *(const float4*)&bias[n0];
#pragma unroll
    for (int i = 0; i < 4; i++) {
        int m = bm * BM + ty * 4 + i;
        float4 o;
        o.x = acc[i][0] + bsv.x;
        o.y = acc[i][1] + bsv.y;
        o.z = acc[i][2] + bsv.z;
        o.w = acc[i][3] + bsv.w;
        *(float4*)&C[(size_t)m * 512 + n0] = o;
    }
}

// ---------------------------------------------------------------------------
// NN SGEMM for M = W_y @ W_out (512x512x512).
// ---------------------------------------------------------------------------
__global__ __launch_bounds__(256) void gemm_nn_M(const float* __restrict__ A,
                                                 const float* __restrict__ B,
                                                 float* __restrict__ C) {
    __shared__ float Ast[BK][BM + 4];
    __shared__ float Bst[BK][BN + 4];
    const int bn = blockIdx.x;
    const int bm = blockIdx.y;
    const int tid = threadIdx.x;

    const int ar = tid >> 2;
    const int ak = (tid & 3) << 2;
    const int br = tid >> 4;
    const int bc = (tid & 15) << 2;
    const int tx = tid & 15;
    const int ty = tid >> 4;

    float acc[4][4];
#pragma unroll
    for (int i = 0; i < 4; i++)
#pragma unroll
        for (int j = 0; j < 4; j++) acc[i][j] = 0.0f;

    for (int kt = 0; kt < 512; kt += BK) {
        float4 av = *(const float4*)(A + (size_t)(bm * BM + ar) * 512 + kt + ak);
        Ast[ak + 0][ar] = av.x; Ast[ak + 1][ar] = av.y;
        Ast[ak + 2][ar] = av.z; Ast[ak + 3][ar] = av.w;
        float4 bv = *(const float4*)(B + (size_t)(kt + br) * 512 + bn * BN + bc);
        *(float4*)&Bst[br][bc] = bv;
        __syncthreads();
#pragma unroll
        for (int kk = 0; kk < BK; kk++) {
            float4 a4 = *(const float4*)&Ast[kk][ty * 4];
            float4 b4 = *(const float4*)&Bst[kk][tx * 4];
#pragma unroll
            for (int i = 0; i < 4; i++) {
                float av_ = (&a4.x)[i];
                acc[i][0] = fmaf(av_, b4.x, acc[i][0]);
                acc[i][1] = fmaf(av_, b4.y, acc[i][1]);
                acc[i][2] = fmaf(av_, b4.z, acc[i][2]);
                acc[i][3] = fmaf(av_, b4.w, acc[i][3]);
            }
        }
        __syncthreads();
    }

    const int n0 = bn * BN + tx * 4;
#pragma unroll
    for (int i = 0; i < 4; i++) {
        int m = bm * BM + ty * 4 + i;
        float4 o = make_float4(acc[i][0], acc[i][1], acc[i][2], acc[i][3]);
        *(float4*)&C[(size_t)m * 512 + n0] = o;
    }
}

// c[i] = b_y[i] + dot(W_y[i,:], b_out)
__global__ void calc_c_kernel(const float* __restrict__ W_y,
                              const float* __restrict__ b_y,
                              const float* __restrict__ b_out,
                              float* __restrict__ c) {
    int row = blockIdx.x * 8 + (threadIdx.x >> 5);
    int l = threadIdx.x & 31;
    float s = 0.0f;
    for (int j = l; j < 512; j += 32) s += W_y[row * 512 + j] * b_out[j];
#pragma unroll
    for (int off = 16; off; off >>= 1) s += __shfl_xor_sync(0xffffffffu, s, off);
    if (l == 0) c[row] = s + b_y[row];
}

// ---------------------------------------------------------------------------
// Warp matvec tile for the grid-barrier fallback.
// ---------------------------------------------------------------------------
__device__ __forceinline__ float matvec_tile(const float* __restrict__ sW,
                                             const float* __restrict__ sA,
                                             int kc, int bg2, int rg2) {
    const float* wp = sW + (rg2 * 8) * 512 + kc;
    const float* ap = sA + (bg2 * 4) * 512 + kc;
    float acc[32];
#pragma unroll
    for (int a = 0; a < 32; a++) acc[a] = 0.0f;
#pragma unroll
    for (int j = 0; j < 16; j++) {
        const int k = 32 * j;
        float yv[4], wv[8];
#pragma unroll
        for (int i2 = 0; i2 < 4; i2++) yv[i2] = ap[i2 * 512 + k];
#pragma unroll
        for (int p = 0; p < 8; p++) wv[p] = wp[p * 512 + k];
#pragma unroll
        for (int i2 = 0; i2 < 4; i2++)
#pragma unroll
            for (int p = 0; p < 8; p++)
                acc[i2 * 8 + p] = fmaf(yv[i2], wv[p], acc[i2 * 8 + p]);
    }
#pragma unroll
    for (int s = 16; s >= 1; s >>= 1) {
        const bool up = (kc & s);
#pragma unroll
        for (int a = 0; a < s; a++) {
            float send = up ? acc[a] : acc[a + s];
            float recv = __shfl_xor_sync(0xffffffffu, send, s);
            acc[a] = (up ? acc[a + s] : acc[a]) + recv;
        }
    }
    return acc[0];
}

extern __shared__ float smem[];

// ---------------------------------------------------------------------------
// Primary scan (R13 + micro-opts): h_t = tanh(xin_t + M h_{t-1} + c),
// 32 clusters x 4 CTAs, 256 threads.
// K [0,256) weights in row-major SMEM; K [256,512) in registers (k-pairs).
// Micro-opts vs R13:
//   - remote push addresses precomputed once (mapa hoisted out of loop)
//   - j=0 weight slice prefetched from SMEM BEFORE cluster_wait
// Split cluster barrier: push -> arrive -> (STG h, prefetch xin) -> wait.
// ---------------------------------------------------------------------------
__global__ __launch_bounds__(256, 1) void jordan_scan_m_cluster4(
    float* __restrict__ out_h) {
    float* sW    = smem;                          // 128 * 256 floats (128 KB)
    float* hbuf0 = smem + ROWS_C * KHALF;         // 2*512
    float* hbuf1 = hbuf0 + BPCL * 512;            // 2*512

    const int tid = threadIdx.x;
    unsigned rank;
    asm("mov.u32 %0, %%cluster_ctarank;" : "=r"(rank));
    const int cid = blockIdx.x / CSZ;
    const int b0 = cid * BPCL;
    const int r0row = (int)rank * ROWS_C;

    const int w = tid >> 5, kc = tid & 31;

    // SMEM weights: K-half [0,256), row-major.
    for (int q = tid; q < ROWS_C * (KHALF / 4); q += 256) {
        int r = q >> 6;
        int k4 = (q & 63) << 2;
        *(float4*)&sW[r * KHALF + k4] =
            *(const float4*)(g_M + (size_t)(r0row + r) * 512 + k4);
    }

    // Register weights: k in [256,512) as packed pairs.
    u64t wreg2[16][4];
#pragma unroll
    for (int r2 = 0; r2 < 16; r2++) {
        const float* mp = g_M + (size_t)(r0row + w * 16 + r2) * 512;
#pragma unroll
        for (int j = 0; j < 4; j++)
            wreg2[r2][j] = *(const u64t*)&mp[KHALF + 2 * kc + 64 * j];
    }

    const int row_l = w * 16 + (kc >> 1);
    const int b_l = kc & 1;
    const int b_idx = b0 + b_l;
    const int r_idx = r0row + row_l;
    const float cv = g_c[r_idx];

    // Precompute all remote push addresses once (mapa hoisted).
    uint32_t r_h[2][CSZ];
    {
        const uint32_t lh0 = smem_u32(&hbuf0[b_l * 512 + r_idx]);
        const uint32_t lh1 = smem_u32(&hbuf1[b_l * 512 + r_idx]);
#pragma unroll
        for (int pr = 0; pr < CSZ; pr++) {
            r_h[0][pr] = mapa_u32(lh0, pr);
            r_h[1][pr] = mapa_u32(lh1, pr);
        }
    }

    __syncthreads();
    cluster_arrive();
    cluster_wait();

    // t = 0: h_0 = tanh(xin_0 + r0)
    float xin_cur = g_xin[((size_t)b_idx * Tdim + 0) * Hdim + r_idx];
    {
        float v = tanhf(xin_cur + g_r0[(size_t)b_idx * 512 + r_idx]);
#pragma unroll
        for (int pr = 0; pr < CSZ; pr++) st_cluster_f32(r_h[0][pr], v);
        cluster_arrive();
        out_h[((size_t)b_idx * Tdim + 0) * Hdim + r_idx] = v;
        xin_cur = g_xin[((size_t)b_idx * Tdim + 1) * Hdim + r_idx];
    }

    const float* sWw = sW + (w * 16) * KHALF;
    const int k0 = 2 * kc;   // j=0 SMEM weight column for this lane

    // Prefetch j=0 weight slice for the first iteration (hb-independent).
    u64t wpre[16];
#pragma unroll
    for (int r2 = 0; r2 < 16; r2++)
        wpre[r2] = *(const u64t*)&sWw[r2 * KHALF + k0];

    for (int t = 1; t < Tdim; t++) {
        cluster_wait();   // h_{t-1} visible in hbuf[(t+1)&1]
        const float* hb = ((t & 1) == 1) ? hbuf0 : hbuf1;

        u64t acc2[16][2];
#pragma unroll
        for (int r2 = 0; r2 < 16; r2++) {
            acc2[r2][0] = 0ull;
            acc2[r2][1] = 0ull;
        }

        // j = 0: weights already in registers (prefetched before wait).
        {
            const u64t ya = *(const u64t*)&hb[k0];
            const u64t yb = *(const u64t*)&hb[512 + k0];
#pragma unroll
            for (int r2 = 0; r2 < 16; r2++) {
                ffma2(acc2[r2][0], wpre[r2], ya);
                ffma2(acc2[r2][1], wpre[r2], yb);
            }
        }
        // j = 1..3: weights from row-major SMEM.
#pragma unroll
        for (int j = 1; j < 4; j++) {
            const int k = k0 + 64 * j;
            const u64t ya = *(const u64t*)&hb[k];
            const u64t yb = *(const u64t*)&hb[512 + k];
#pragma unroll
            for (int r2 = 0; r2 < 16; r2++) {
                const u64t wp = *(const u64t*)&sWw[r2 * KHALF + k];
                ffma2(acc2[r2][0], wp, ya);
                ffma2(acc2[r2][1], wp, yb);
            }
        }
        // K [256,512): weights from registers.
#pragma unroll
        for (int j = 0; j < 4; j++) {
            const int k = KHALF + k0 + 64 * j;
            const u64t ya = *(const u64t*)&hb[k];
            const u64t yb = *(const u64t*)&hb[512 + k];
#pragma unroll
            for (int r2 = 0; r2 < 16; r2++) {
                ffma2(acc2[r2][0], wreg2[r2][j], ya);
                ffma2(acc2[r2][1], wreg2[r2][j], yb);
            }
        }

        float acc_f[32];
#pragma unroll
        for (int r2 = 0; r2 < 16; r2++) {
            float2 s0 = unpk2(acc2[r2][0]);
            float2 s1 = unpk2(acc2[r2][1]);
            acc_f[2 * r2 + 0] = s0.x + s0.y;
            acc_f[2 * r2 + 1] = s1.x + s1.y;
        }

#pragma unroll
        for (int s = 16; s >= 1; s >>= 1) {
            const bool up = (kc & s);
#pragma unroll
            for (int a = 0; a < s; a++) {
                float send = up ? acc_f[a] : acc_f[a + s];
                float recv = __shfl_xor_sync(0xffffffffu, send, s);
                acc_f[a] = (up ? acc_f[a + s] : acc_f[a]) + recv;
            }
        }

        float v = tanhf(acc_f[0] + xin_cur + cv);
        const int wb = t & 1;
#pragma unroll
        for (int pr = 0; pr < CSZ; pr++) st_cluster_f32(r_h[wb][pr], v);
        cluster_arrive();
        // Window: off-critical-path work between arrive and next wait.
        out_h[((size_t)b_idx * Tdim + t) * Hdim + r_idx] = v;
        if (t + 1 < Tdim)
            xin_cur = g_xin[((size_t)b_idx * Tdim + (t + 1)) * Hdim + r_idx];
    }
    cluster_wait();   // balance final arrive; keep smem alive for peers
}

// ---------------------------------------------------------------------------
// Fallback scan: grid barrier (128 CTAs), ONE barrier/step.
// ---------------------------------------------------------------------------
__global__ __launch_bounds__(256, 1) void jordan_scan_m(
    float* __restrict__ out_h) {
    float* sM   = smem;
    float* sAct = smem + RPB * 512;

    const int tid = threadIdx.x;
    const int bid = blockIdx.x;
    const int rg = bid & 31;
    const int bg = bid >> 5;
    const int r0 = rg * RPB;
    const int b0 = bg * BPB;

    for (int q = tid; q < RPB * 512 / 4; q += 256)
        ((float4*)sM)[q] = ((const float4*)(g_M + (size_t)r0 * 512))[q];

    const int w = tid >> 5, kc = tid & 31;
    const int bg2 = w >> 1, rg2 = w & 1;
    const int i2 = kc >> 3, p = kc & 7;
    const int b_idx = b0 + bg2 * 4 + i2;
    const int r_idx = r0 + rg2 * 8 + p;
    const float cv = g_c[r_idx];

    const int sb = tid >> 4;
    const int sc = tid & 15;

    __syncthreads();

    {
        float v = tanhf(g_xin[((size_t)b_idx * Tdim + 0) * Hdim + r_idx] +
                        g_r0[(size_t)b_idx * 512 + r_idx]);
        out_h[((size_t)b_idx * Tdim + 0) * Hdim + r_idx] = v;
    }
    __threadfence();
    gridbar();

    for (int t = 1; t < Tdim; t++) {
        {
            const float* src = out_h + ((size_t)(b0 + sb) * Tdim + (t - 1)) * Hdim;
            float4* dst = (float4*)(sAct + sb * 512);
            const float4* s4 = (const float4*)src;
#pragma unroll
            for (int q = 0; q < 8; q++) dst[sc + 16 * q] = s4[sc + 16 * q];
        }
        __syncthreads();

        float v = matvec_tile(sM, sAct, kc, bg2, rg2);
        v = tanhf(v + g_xin[((size_t)b_idx * Tdim + t) * Hdim + r_idx] + cv);
        out_h[((size_t)b_idx * Tdim + t) * Hdim + r_idx] = v;
        __threadfence();
        gridbar();
    }
}

// ---------------------------------------------------------------------------
extern "C" void kernel_launch(void* const* d_in, const int* in_sizes, int n_in,
                              void* d_out, int out_size) {
    const float* emb    = (const float*)d_in[0];
    const float* lastlg = (const float*)d_in[1];
    const float* W_in   = (const float*)d_in[2];
    const float* b_in   = (const float*)d_in[3];
    const float* W_y    = (const float*)d_in[4];
    const float* b_y    = (const float*)d_in[5];
    const float* W_out  = (const float*)d_in[6];
    const float* b_out  = (const float*)d_in[7];

    float* out    = (float*)d_out;
    float* out_h  = out;
    float* out_y  = out + (size_t)Bdim * Tdim * Hdim;
    float* out_yl = out + (size_t)2 * Bdim * Tdim * Hdim;

    float* xin_p; cudaGetSymbolAddress((void**)&xin_p, g_xin);
    float* M_p;   cudaGetSymbolAddress((void**)&M_p, g_M);
    float* r0_p;  cudaGetSymbolAddress((void**)&r0_p, g_r0);
    float* c_p;   cudaGetSymbolAddress((void**)&c_p, g_c);

    // Precomputes
    gemm_nn_M<<<dim3(512 / BN, 512 / BM), 256>>>(W_y, W_out, M_p);
    calc_c_kernel<<<64, 256>>>(W_y, b_y, b_out, c_p);
    gemm_nt<<<dim3(512 / BN, Bdim / BM), 256>>>(lastlg, W_y, b_y, r0_p);

    // Input projection (fast path)
    gemm_nt2<<<dim3(512 / 128, (Bdim * Tdim) / 128), 256>>>(emb, W_in, b_in,
                                                            xin_p, nullptr);

    // ---- scan: try 4-CTA cluster path ----
    const int smem_cluster =
        (ROWS_C * KHALF + 2 * BPCL * 512) * (int)sizeof(float);  // 136 KB
    bool use_cluster =
        (cudaFuncSetAttribute(jordan_scan_m_cluster4,
                              cudaFuncAttributeMaxDynamicSharedMemorySize,
                              smem_cluster) == cudaSuccess);

    cudaLaunchConfig_t cfg = {};
    cfg.gridDim = dim3(CSZ * NCL, 1, 1);
    cfg.blockDim = dim3(256, 1, 1);
    cfg.dynamicSmemBytes = smem_cluster;
    cudaLaunchAttribute attrs[1];
    attrs[0].id = cudaLaunchAttributeClusterDimension;
    attrs[0].val.clusterDim.x = CSZ;
    attrs[0].val.clusterDim.y = 1;
    attrs[0].val.clusterDim.z = 1;
    cfg.attrs = attrs;
    cfg.numAttrs = 1;

    if (use_cluster) {
        int maxClusters = 0;
        cudaError_t st = cudaOccupancyMaxActiveClusters(&maxClusters,
                                                        jordan_scan_m_cluster4,
                                                        &cfg);
        if (st != cudaSuccess || maxClusters < NCL) use_cluster = false;
    }
    (void)cudaGetLastError();

    if (use_cluster) {
        cudaError_t st = cudaLaunchKernelEx(&cfg, jordan_scan_m_cluster4, out_h);
        if (st != cudaSuccess) {
            (void)cudaGetLastError();
            use_cluster = false;
        }
    }
    if (!use_cluster) {
        const int smem_fb = 2 * RPB * 512 * (int)sizeof(float);  // 64 KB
        cudaFuncSetAttribute(jordan_scan_m,
                             cudaFuncAttributeMaxDynamicSharedMemorySize, smem_fb);
        jordan_scan_m<<<NBLK, 256, smem_fb>>>(out_h);
    }

    // Epilogue: y = h @ W_out^T + b_out (+ y_last rows), fast path
    gemm_nt2<<<dim3(512 / 128, (Bdim * Tdim) / 128), 256>>>(out_h, W_out, b_out,
                                                            out_y, out_yl);
}